// round 2
// baseline (speedup 1.0000x reference)
#include <cuda_runtime.h>
#include <math.h>
#include <stdint.h>
#include <stddef.h>

// Problem dims (fixed by the dataset)
#define BD   2560      // B*D word-level sequences
#define SW   50        // word-level T
#define EW   200       // embedding
#define HH   128       // GRU hidden
#define BB   64        // batch (docs)
#define DD   40        // sentences per doc
#define GC   256       // gate cols = 2H (also bigru output width)
#define CC   128       // candidate cols = H

// ---------------- scratch (device globals; no allocation allowed) ----------------
__device__ float g_XWg_f[(size_t)BD*SW*GC];
__device__ float g_XWc_f[(size_t)BD*SW*CC];
__device__ float g_XWg_b[(size_t)BD*SW*GC];
__device__ float g_XWc_b[(size_t)BD*SW*CC];
__device__ float g_low  [(size_t)BD*SW*GC];
__device__ float g_proj [(size_t)BD*SW*CC];
__device__ float g_hf[BD*HH];
__device__ float g_hb[BD*HH];
__device__ float g_sent[BD*GC];
__device__ float g_sXWg_f[BB*DD*GC];
__device__ float g_sXWc_f[BB*DD*CC];
__device__ float g_sXWg_b[BB*DD*GC];
__device__ float g_sXWc_b[BB*DD*CC];
__device__ float g_high[BB*DD*GC];
__device__ float g_shf[BB*HH];
__device__ float g_shb[BB*HH];
__device__ float g_docvec[BB*GC];

// ---------------- zero the recurrent states ----------------
__global__ void zero_h_kernel() {
    int i = blockIdx.x * blockDim.x + threadIdx.x;
    if (i < BD*HH) { g_hf[i] = 0.f; g_hb[i] = 0.f; }
    if (i < BB*HH) { g_shf[i] = 0.f; g_shb[i] = 0.f; }
}

// ---------------- generic fp32 GEMM: C = A[MxK] @ W[KxN] + bias, optional tanh ----
// Requires: M % 128 == 0, N % 128 == 0, K % 4 == 0.
__global__ void sgemm_bias(const float* __restrict__ A, const float* __restrict__ W,
                           const float* __restrict__ bias, float* __restrict__ C,
                           int M, int N, int K, int act)
{
    __shared__ float As[16][128];
    __shared__ float Bs[16][128];
    const int tid = threadIdx.x;
    const int m0 = blockIdx.x * 128;
    const int n0 = blockIdx.y * 128;
    const int tx = tid & 15;
    const int ty = tid >> 4;

    float acc[8][8];
#pragma unroll
    for (int i = 0; i < 8; i++)
#pragma unroll
        for (int j = 0; j < 8; j++) acc[i][j] = 0.f;

    for (int k0 = 0; k0 < K; k0 += 16) {
        // A tile (transposed into As[k][row])
#pragma unroll
        for (int i = 0; i < 2; i++) {
            int f4  = i * 256 + tid;
            int row = f4 >> 2;
            int kg  = (f4 & 3) * 4;
            float4 v = make_float4(0.f, 0.f, 0.f, 0.f);
            if (k0 + kg < K) v = *(const float4*)(A + (size_t)(m0 + row) * K + k0 + kg);
            As[kg + 0][row] = v.x; As[kg + 1][row] = v.y;
            As[kg + 2][row] = v.z; As[kg + 3][row] = v.w;
        }
        // B tile
#pragma unroll
        for (int i = 0; i < 2; i++) {
            int f4 = i * 256 + tid;
            int kr = f4 >> 5;
            int nc = (f4 & 31) * 4;
            float4 v = make_float4(0.f, 0.f, 0.f, 0.f);
            if (k0 + kr < K) v = *(const float4*)(W + (size_t)(k0 + kr) * N + n0 + nc);
            *(float4*)&Bs[kr][nc] = v;
        }
        __syncthreads();
#pragma unroll
        for (int k = 0; k < 16; k++) {
            float a[8], b[8];
            *(float4*)&a[0] = *(const float4*)&As[k][ty * 8];
            *(float4*)&a[4] = *(const float4*)&As[k][ty * 8 + 4];
            *(float4*)&b[0] = *(const float4*)&Bs[k][tx * 8];
            *(float4*)&b[4] = *(const float4*)&Bs[k][tx * 8 + 4];
#pragma unroll
            for (int i = 0; i < 8; i++)
#pragma unroll
                for (int j = 0; j < 8; j++) acc[i][j] += a[i] * b[j];
        }
        __syncthreads();
    }

#pragma unroll
    for (int i = 0; i < 8; i++) {
        int m = m0 + ty * 8 + i;
#pragma unroll
        for (int j = 0; j < 8; j++) {
            float v = acc[i][j] + bias[n0 + tx * 8 + j];
            if (act) v = tanhf(v);
            C[(size_t)m * N + n0 + tx * 8 + j] = v;
        }
    }
}

// ---------------- GRU step kernel (one time step, both directions via gridDim.y) --
// TF GRUCell with dynamic_rnn length masking; bw direction implements
// reverse_seq(gru(reverse_seq(x))) by index remapping (te = len-1-t).
// SR = sequences per thread-row (SPB = 4*SR sequences per block), 256 threads.
template<int SR>
__global__ void gru_step_kernel(
    const float* __restrict__ XWg0, const float* __restrict__ XWg1,
    const float* __restrict__ XWc0, const float* __restrict__ XWc1,
    const float* __restrict__ Wgh0, const float* __restrict__ Wgh1,
    const float* __restrict__ Wch0, const float* __restrict__ Wch1,
    const int*   __restrict__ lens,
    float* __restrict__ h0p, float* __restrict__ h1p,
    float* __restrict__ outp,
    int N, int T, int t)
{
    constexpr int SPB = SR * 4;
    const int dir = blockIdx.y;
    const float* XWg = dir ? XWg1 : XWg0;
    const float* XWc = dir ? XWc1 : XWc0;
    const float* Wgh = dir ? Wgh1 : Wgh0;
    const float* Wch = dir ? Wch1 : Wch0;
    float* hst = dir ? h1p : h0p;
    const int col_off = dir * CC;

    extern __shared__ float smem[];
    float* sh  = smem;                    // SPB*HH
    float* srh = sh  + SPB * HH;          // SPB*HH
    float* sz  = srh + SPB * HH;          // SPB*HH
    float* wt  = sz  + SPB * HH;          // 16*GC (gate) / 16*CC (cand)
    int*   slen = (int*)(wt + 16 * GC);

    const int tid = threadIdx.x;
    const int nb  = blockIdx.x * SPB;

    if (tid < SPB) slen[tid] = lens[nb + tid];
    {
        const float4* src = (const float4*)(hst + (size_t)nb * HH);
        float4* dst = (float4*)sh;
        for (int i = tid; i < SPB * HH / 4; i += 256) dst[i] = src[i];
    }
    __syncthreads();

    const int ct = tid & 63;
    const int rt = tid >> 6;
    const int j0 = ct * 4;
    const int s0 = rt * SR;

    // ---------- gate phase: acc = h @ Wgh (128 x 256) ----------
    float acc[SR][4];
#pragma unroll
    for (int s = 0; s < SR; s++) { acc[s][0]=0.f; acc[s][1]=0.f; acc[s][2]=0.f; acc[s][3]=0.f; }

    for (int kc = 0; kc < HH; kc += 16) {
        __syncthreads();
        {
            const float4* src = (const float4*)(Wgh + (size_t)kc * GC);
            float4* dst = (float4*)wt;
            for (int i = tid; i < 16 * GC / 4; i += 256) dst[i] = src[i];
        }
        __syncthreads();
#pragma unroll
        for (int k = 0; k < 16; k += 4) {
            float4 w0 = *(const float4*)(wt + (k + 0) * GC + j0);
            float4 w1 = *(const float4*)(wt + (k + 1) * GC + j0);
            float4 w2 = *(const float4*)(wt + (k + 2) * GC + j0);
            float4 w3 = *(const float4*)(wt + (k + 3) * GC + j0);
#pragma unroll
            for (int s = 0; s < SR; s++) {
                float4 hv = *(const float4*)(sh + (s0 + s) * HH + kc + k);
                acc[s][0] += hv.x*w0.x + hv.y*w1.x + hv.z*w2.x + hv.w*w3.x;
                acc[s][1] += hv.x*w0.y + hv.y*w1.y + hv.z*w2.y + hv.w*w3.y;
                acc[s][2] += hv.x*w0.z + hv.y*w1.z + hv.z*w2.z + hv.w*w3.z;
                acc[s][3] += hv.x*w0.w + hv.y*w1.w + hv.z*w2.w + hv.w*w3.w;
            }
        }
    }

    // gate epilogue: r,z = sigmoid(acc + XWg); store r*h and z
#pragma unroll
    for (int s = 0; s < SR; s++) {
        int sl = s0 + s;
        int n  = nb + sl;
        int L  = slen[sl];
        int te = dir ? ((t < L) ? (L - 1 - t) : t) : t;
        float4 xg = *(const float4*)(XWg + ((size_t)n * T + te) * GC + j0);
        float gg0 = 1.f / (1.f + expf(-(acc[s][0] + xg.x)));
        float gg1 = 1.f / (1.f + expf(-(acc[s][1] + xg.y)));
        float gg2 = 1.f / (1.f + expf(-(acc[s][2] + xg.z)));
        float gg3 = 1.f / (1.f + expf(-(acc[s][3] + xg.w)));
        if (ct < 32) { // r half: j0 in [0,128)
            float4 hv = *(const float4*)(sh + sl * HH + j0);
            float4 o; o.x = gg0*hv.x; o.y = gg1*hv.y; o.z = gg2*hv.z; o.w = gg3*hv.w;
            *(float4*)(srh + sl * HH + j0) = o;
        } else {       // z half
            float4 o; o.x = gg0; o.y = gg1; o.z = gg2; o.w = gg3;
            *(float4*)(sz + sl * HH + (j0 - 128)) = o;
        }
    }

    // ---------- candidate phase: acc2 = (r*h) @ Wch (128 x 128) ----------
    const int j2 = ct * 2;
    float acc2[SR][2];
#pragma unroll
    for (int s = 0; s < SR; s++) { acc2[s][0] = 0.f; acc2[s][1] = 0.f; }

    for (int kc = 0; kc < HH; kc += 16) {
        __syncthreads();   // also publishes srh/sz on first iteration
        {
            const float4* src = (const float4*)(Wch + (size_t)kc * CC);
            float4* dst = (float4*)wt;
            for (int i = tid; i < 16 * CC / 4; i += 256) dst[i] = src[i];
        }
        __syncthreads();
#pragma unroll
        for (int k = 0; k < 16; k += 4) {
            float2 w0 = *(const float2*)(wt + (k + 0) * CC + j2);
            float2 w1 = *(const float2*)(wt + (k + 1) * CC + j2);
            float2 w2 = *(const float2*)(wt + (k + 2) * CC + j2);
            float2 w3 = *(const float2*)(wt + (k + 3) * CC + j2);
#pragma unroll
            for (int s = 0; s < SR; s++) {
                float4 hv = *(const float4*)(srh + (s0 + s) * HH + kc + k);
                acc2[s][0] += hv.x*w0.x + hv.y*w1.x + hv.z*w2.x + hv.w*w3.x;
                acc2[s][1] += hv.x*w0.y + hv.y*w1.y + hv.z*w2.y + hv.w*w3.y;
            }
        }
    }

    // final epilogue: c = tanh(acc2 + XWc); h' = z*h + (1-z)*c with masking
#pragma unroll
    for (int s = 0; s < SR; s++) {
        int sl = s0 + s;
        int n  = nb + sl;
        int L  = slen[sl];
        bool valid = (t < L);
        int te = dir ? (valid ? (L - 1 - t) : t) : t;   // input index == output index
        float2 xc = *(const float2*)(XWc + ((size_t)n * T + te) * CC + j2);
        float c0 = tanhf(acc2[s][0] + xc.x);
        float c1 = tanhf(acc2[s][1] + xc.y);
        float z0 = sz[sl * HH + j2], z1 = sz[sl * HH + j2 + 1];
        float h0 = sh[sl * HH + j2], h1 = sh[sl * HH + j2 + 1];
        float hn0 = z0 * h0 + (1.f - z0) * c0;
        float hn1 = z1 * h1 + (1.f - z1) * c1;
        float2 hw; hw.x = valid ? hn0 : h0; hw.y = valid ? hn1 : h1;
        *(float2*)(hst + (size_t)n * HH + j2) = hw;
        float2 ov; ov.x = valid ? hn0 : 0.f; ov.y = valid ? hn1 : 0.f;
        *(float2*)(outp + ((size_t)n * T + te) * GC + col_off + j2) = ov;
    }
}

// ---------------- attention: score = proj @ u; softmax over T; vec = att @ seq ----
__global__ void attention_kernel(const float* __restrict__ proj,  // [N*T*128]
                                 const float* __restrict__ u,     // [128]
                                 const float* __restrict__ seq,   // [N*T*256]
                                 float* __restrict__ vec,         // [N*256]
                                 float* __restrict__ att_out,     // [N*T]
                                 int N, int T)
{
    const int n = blockIdx.x;
    const int tid = threadIdx.x;
    const int warp = tid >> 5, lane = tid & 31;
    __shared__ float su[128];
    __shared__ float sc[64];
    __shared__ float red[2];
    if (tid < 128) su[tid] = u[tid];
    __syncthreads();

    for (int t = warp; t < T; t += 8) {
        const float* pr = proj + ((size_t)n * T + t) * 128;
        float p = 0.f;
#pragma unroll
        for (int i = 0; i < 4; i++) p += pr[lane + i * 32] * su[lane + i * 32];
#pragma unroll
        for (int o = 16; o > 0; o >>= 1) p += __shfl_xor_sync(0xffffffffu, p, o);
        if (lane == 0) sc[t] = p;
    }
    __syncthreads();
    if (tid == 0) {
        float m = sc[0];
        for (int t = 1; t < T; t++) m = fmaxf(m, sc[t]);
        float s = 0.f;
        for (int t = 0; t < T; t++) s += expf(sc[t] - m);
        red[0] = m; red[1] = s;
    }
    __syncthreads();
    if (tid < T) {
        float a = expf(sc[tid] - red[0]) / red[1];
        att_out[(size_t)n * T + tid] = a;
        sc[tid] = a;
    }
    __syncthreads();
    // weighted sum over T for all 256 channels
    {
        int c = tid;
        float a = 0.f;
        for (int t = 0; t < T; t++) a += sc[t] * seq[((size_t)n * T + t) * 256 + c];
        vec[(size_t)n * 256 + c] = a;
    }
}

// ---------------- final: logits, log-softmax, loss, reg, predict, accuracy -------
__global__ void final_kernel(const float* __restrict__ docvec, const float* __restrict__ wp,
                             const float* __restrict__ bp, const int* __restrict__ y,
                             const float* __restrict__ wa_l, const float* __restrict__ ba_l,
                             const float* __restrict__ wa_h, const float* __restrict__ uw,
                             const float* __restrict__ us, float* __restrict__ out)
{
    __shared__ float slog[640];
    __shared__ float red[256];
    __shared__ float lossb[64];
    __shared__ int corr[64];
    const int tid = threadIdx.x;

    for (int idx = tid; idx < 640; idx += 256) {
        int b = idx / 10, c = idx % 10;
        float a = bp[c];
        for (int k = 0; k < 256; k++) a += docvec[b * 256 + k] * wp[k * 10 + c];
        slog[idx] = a;
    }
    __syncthreads();
    if (tid < 64) {
        int b = tid;
        float m = slog[b * 10]; int am = 0;
        for (int c = 1; c < 10; c++) { float v = slog[b * 10 + c]; if (v > m) { m = v; am = c; } }
        float s = 0.f;
        for (int c = 0; c < 10; c++) s += expf(slog[b * 10 + c] - m);
        float lse = m + logf(s);
        int yb = y[b];
        lossb[b] = lse - slog[b * 10 + yb];
        corr[b]  = (am == yb) ? 1 : 0;
        out[1 + b] = (float)am;
    }
    // regularizer: sum(wa_l^2) + sum(ba_l^2) + 2*sum(wa_h^2) + sum(uw^2) + sum(us^2)
    float r = 0.f;
    for (int i = tid; i < 256 * 128; i += 256) {
        float v = wa_l[i]; r += v * v;
        float w = wa_h[i]; r += 2.f * w * w;
    }
    for (int i = tid; i < 128; i += 256) {
        float v = ba_l[i]; r += v * v;
        float a = uw[i];   r += a * a;
        float b2 = us[i];  r += b2 * b2;
    }
    red[tid] = r;
    __syncthreads();
    for (int o = 128; o > 0; o >>= 1) { if (tid < o) red[tid] += red[tid + o]; __syncthreads(); }
    if (tid == 0) {
        float L = 0.f; int C = 0;
        for (int b = 0; b < 64; b++) { L += lossb[b]; C += corr[b]; }
        out[0]  = L / 64.f + 0.01f * red[0];
        out[65] = (float)C / 64.f;
    }
}

// =================================================================================
extern "C" void kernel_launch(void* const* d_in, const int* in_sizes, int n_in,
                              void* d_out, int out_size)
{
    (void)in_sizes; (void)out_size;
    const float* X    = (const float*)d_in[0];
    const int*   y    = (const int*)d_in[1];
    const int*   slen = (const int*)d_in[2];
    const int*   dlen = (const int*)d_in[3];
    // dropout / is_training may or may not appear as inputs 4,5
    const int wo = (n_in >= 30) ? 6 : (n_in - 24);
    const float* Wt[24];
    for (int i = 0; i < 24; i++) Wt[i] = (const float*)d_in[wo + i];
    const float *wgf_l = Wt[0],  *bgf_l = Wt[1],  *wcf_l = Wt[2],  *bcf_l = Wt[3];
    const float *wgb_l = Wt[4],  *bgb_l = Wt[5],  *wcb_l = Wt[6],  *bcb_l = Wt[7];
    const float *wa_l  = Wt[8],  *ba_l  = Wt[9];
    const float *wgf_h = Wt[10], *bgf_h = Wt[11], *wcf_h = Wt[12], *bcf_h = Wt[13];
    const float *wgb_h = Wt[14], *bgb_h = Wt[15], *wcb_h = Wt[16], *bcb_h = Wt[17];
    const float *wa_h  = Wt[18], *ba_h  = Wt[19];
    const float *uw = Wt[20], *us = Wt[21], *wp = Wt[22], *bp = Wt[23];
    float* out = (float*)d_out;

    float *XWg_f, *XWc_f, *XWg_b, *XWc_b, *low, *proj, *hf, *hb, *sent;
    float *sXWg_f, *sXWc_f, *sXWg_b, *sXWc_b, *high, *shf, *shb, *docvec;
    cudaGetSymbolAddress((void**)&XWg_f, g_XWg_f);
    cudaGetSymbolAddress((void**)&XWc_f, g_XWc_f);
    cudaGetSymbolAddress((void**)&XWg_b, g_XWg_b);
    cudaGetSymbolAddress((void**)&XWc_b, g_XWc_b);
    cudaGetSymbolAddress((void**)&low,   g_low);
    cudaGetSymbolAddress((void**)&proj,  g_proj);
    cudaGetSymbolAddress((void**)&hf,    g_hf);
    cudaGetSymbolAddress((void**)&hb,    g_hb);
    cudaGetSymbolAddress((void**)&sent,  g_sent);
    cudaGetSymbolAddress((void**)&sXWg_f, g_sXWg_f);
    cudaGetSymbolAddress((void**)&sXWc_f, g_sXWc_f);
    cudaGetSymbolAddress((void**)&sXWg_b, g_sXWg_b);
    cudaGetSymbolAddress((void**)&sXWc_b, g_sXWc_b);
    cudaGetSymbolAddress((void**)&high,  g_high);
    cudaGetSymbolAddress((void**)&shf,   g_shf);
    cudaGetSymbolAddress((void**)&shb,   g_shb);
    cudaGetSymbolAddress((void**)&docvec, g_docvec);

    const int smem_gru8 = (3 * 32 * HH + 16 * GC) * 4 + 64 * 4;  // 65792 B
    const int smem_gru2 = (3 * 8  * HH + 16 * GC) * 4 + 64 * 4;
    cudaFuncSetAttribute(gru_step_kernel<8>, cudaFuncAttributeMaxDynamicSharedMemorySize, smem_gru8);

    // 0) zero recurrent states
    zero_h_kernel<<<(BD * HH + 255) / 256, 256>>>();

    // 1) word-level input precompute: x @ W_x + b  (W rows [0,200))
    sgemm_bias<<<dim3(BD * SW / 128, 2), 256>>>(X, wgf_l, bgf_l, XWg_f, BD * SW, GC, EW, 0);
    sgemm_bias<<<dim3(BD * SW / 128, 1), 256>>>(X, wcf_l, bcf_l, XWc_f, BD * SW, CC, EW, 0);
    sgemm_bias<<<dim3(BD * SW / 128, 2), 256>>>(X, wgb_l, bgb_l, XWg_b, BD * SW, GC, EW, 0);
    sgemm_bias<<<dim3(BD * SW / 128, 1), 256>>>(X, wcb_l, bcb_l, XWc_b, BD * SW, CC, EW, 0);

    // 2) word-level BiGRU recurrence (50 steps, both dirs per launch)
    for (int t = 0; t < SW; t++) {
        gru_step_kernel<8><<<dim3(BD / 32, 2), 256, smem_gru8>>>(
            XWg_f, XWg_b, XWc_f, XWc_b,
            wgf_l + (size_t)EW * GC, wgb_l + (size_t)EW * GC,
            wcf_l + (size_t)EW * CC, wcb_l + (size_t)EW * CC,
            slen, hf, hb, low, BD, SW, t);
    }

    // 3) word attention
    sgemm_bias<<<dim3(BD * SW / 128, 1), 256>>>(low, wa_l, ba_l, proj, BD * SW, CC, GC, 1);
    attention_kernel<<<BD, 256>>>(proj, uw, low, sent, out + 66, BD, SW);

    // 4) sentence-level input precompute (W rows [0,256))
    sgemm_bias<<<dim3(BB * DD / 128, 2), 256>>>(sent, wgf_h, bgf_h, sXWg_f, BB * DD, GC, GC, 0);
    sgemm_bias<<<dim3(BB * DD / 128, 1), 256>>>(sent, wcf_h, bcf_h, sXWc_f, BB * DD, CC, GC, 0);
    sgemm_bias<<<dim3(BB * DD / 128, 2), 256>>>(sent, wgb_h, bgb_h, sXWg_b, BB * DD, GC, GC, 0);
    sgemm_bias<<<dim3(BB * DD / 128, 1), 256>>>(sent, wcb_h, bcb_h, sXWc_b, BB * DD, CC, GC, 0);

    // 5) sentence-level BiGRU recurrence (40 steps)
    for (int t = 0; t < DD; t++) {
        gru_step_kernel<2><<<dim3(BB / 8, 2), 256, smem_gru2>>>(
            sXWg_f, sXWg_b, sXWc_f, sXWc_b,
            wgf_h + (size_t)GC * GC, wgb_h + (size_t)GC * GC,
            wcf_h + (size_t)GC * CC, wcb_h + (size_t)GC * CC,
            dlen, shf, shb, high, BB, DD, t);
    }

    // 6) sentence attention
    sgemm_bias<<<dim3(BB * DD / 128, 1), 256>>>(high, wa_h, ba_h, proj, BB * DD, CC, GC, 1);
    attention_kernel<<<BB, 256>>>(proj, us, high, docvec, out + 66 + BD * SW, BB, DD);

    // 7) classifier / loss / reg / predict / accuracy
    final_kernel<<<1, 256>>>(docvec, wp, bp, y, wa_l, ba_l, wa_h, uw, us, out);
}

// round 3
// speedup vs baseline: 1.2114x; 1.2114x over previous
#include <cuda_runtime.h>
#include <math.h>
#include <stdint.h>
#include <stddef.h>

// Problem dims (fixed by the dataset)
#define BD   2560      // B*D word-level sequences
#define SW   50        // word-level T
#define EW   200       // embedding
#define HH   128       // GRU hidden
#define BB   64        // batch (docs)
#define DD   40        // sentences per doc
#define GC   256       // gate cols = 2H (also bigru output width)
#define CC   128       // candidate cols = H

typedef unsigned long long ull;

// ---------------- packed fp32x2 helpers (sm_103a FFMA2 path) ----------------
__device__ __forceinline__ ull ffma2(ull a, ull b, ull c) {
    ull d;
    asm("fma.rn.f32x2 %0, %1, %2, %3;" : "=l"(d) : "l"(a), "l"(b), "l"(c));
    return d;
}
__device__ __forceinline__ ull pack2(float x, float y) {
    ull d;
    asm("mov.b64 %0, {%1, %2};" : "=l"(d) : "r"(__float_as_uint(x)), "r"(__float_as_uint(y)));
    return d;
}
__device__ __forceinline__ float2 unpack2(ull v) {
    unsigned lo, hi;
    asm("mov.b64 {%0, %1}, %2;" : "=r"(lo), "=r"(hi) : "l"(v));
    float2 r; r.x = __uint_as_float(lo); r.y = __uint_as_float(hi);
    return r;
}

// ---------------- scratch (device globals; no allocation allowed) ----------------
__device__ float g_XWg_f[(size_t)BD*SW*GC];
__device__ float g_XWc_f[(size_t)BD*SW*CC];
__device__ float g_XWg_b[(size_t)BD*SW*GC];
__device__ float g_XWc_b[(size_t)BD*SW*CC];
__device__ float g_low  [(size_t)BD*SW*GC];
__device__ float g_proj [(size_t)BD*SW*CC];
__device__ float g_sent[BD*GC];
__device__ float g_sXWg_f[BB*DD*GC];
__device__ float g_sXWc_f[BB*DD*CC];
__device__ float g_sXWg_b[BB*DD*GC];
__device__ float g_sXWc_b[BB*DD*CC];
__device__ float g_high[BB*DD*GC];
__device__ float g_docvec[BB*GC];

// ---------------- generic fp32 GEMM: C = A[MxK] @ W[KxN] + bias, optional tanh ----
// 128x128 tile, FFMA2 inner product, double-buffered smem (1 sync per K-chunk).
// Requires: M % 128 == 0, N % 128 == 0.
__global__ void sgemm_bias(const float* __restrict__ A, const float* __restrict__ W,
                           const float* __restrict__ bias, float* __restrict__ C,
                           int M, int N, int K, int act)
{
    __shared__ __align__(16) float As[2][16][128];
    __shared__ __align__(16) float Bs[2][16][128];
    const int tid = threadIdx.x;
    const int m0 = blockIdx.x * 128;
    const int n0 = blockIdx.y * 128;
    const int tx = tid & 15;
    const int ty = tid >> 4;

    ull acc[8][4];
#pragma unroll
    for (int i = 0; i < 8; i++)
#pragma unroll
        for (int j = 0; j < 4; j++) acc[i][j] = 0ull;

    const int nchunk = (K + 15) / 16;
    float4 la[2], lb[2];

    // ---- load chunk 0 into regs ----
#pragma unroll
    for (int i = 0; i < 2; i++) {
        int f4  = i * 256 + tid;
        int row = f4 >> 2;
        int kg  = (f4 & 3) * 4;
        la[i] = make_float4(0.f, 0.f, 0.f, 0.f);
        if (kg < K) la[i] = *(const float4*)(A + (size_t)(m0 + row) * K + kg);
        int kr = f4 >> 5;
        int nc = (f4 & 31) * 4;
        lb[i] = make_float4(0.f, 0.f, 0.f, 0.f);
        if (kr < K) lb[i] = *(const float4*)(W + (size_t)kr * N + n0 + nc);
    }
    // ---- store chunk 0 into buf 0 ----
#pragma unroll
    for (int i = 0; i < 2; i++) {
        int f4  = i * 256 + tid;
        int row = f4 >> 2;
        int kg  = (f4 & 3) * 4;
        As[0][kg + 0][row] = la[i].x; As[0][kg + 1][row] = la[i].y;
        As[0][kg + 2][row] = la[i].z; As[0][kg + 3][row] = la[i].w;
        int kr = f4 >> 5;
        int nc = (f4 & 31) * 4;
        *(float4*)&Bs[0][kr][nc] = lb[i];
    }
    __syncthreads();

    for (int c = 0; c < nchunk; c++) {
        if (c + 1 < nchunk) {
            const int k0 = (c + 1) * 16;
#pragma unroll
            for (int i = 0; i < 2; i++) {
                int f4  = i * 256 + tid;
                int row = f4 >> 2;
                int kg  = (f4 & 3) * 4;
                la[i] = make_float4(0.f, 0.f, 0.f, 0.f);
                if (k0 + kg < K) la[i] = *(const float4*)(A + (size_t)(m0 + row) * K + k0 + kg);
                int kr = f4 >> 5;
                int nc = (f4 & 31) * 4;
                lb[i] = make_float4(0.f, 0.f, 0.f, 0.f);
                if (k0 + kr < K) lb[i] = *(const float4*)(W + (size_t)(k0 + kr) * N + n0 + nc);
            }
        }
        const int cb = c & 1;
#pragma unroll
        for (int k = 0; k < 16; k++) {
            float4 A0 = *(const float4*)&As[cb][k][ty * 8];
            float4 A1 = *(const float4*)&As[cb][k][ty * 8 + 4];
            ulonglong2 B0 = *(const ulonglong2*)&Bs[cb][k][tx * 8];
            ulonglong2 B1 = *(const ulonglong2*)&Bs[cb][k][tx * 8 + 4];
            ull ap;
            ap = pack2(A0.x, A0.x);
            acc[0][0] = ffma2(ap, B0.x, acc[0][0]); acc[0][1] = ffma2(ap, B0.y, acc[0][1]);
            acc[0][2] = ffma2(ap, B1.x, acc[0][2]); acc[0][3] = ffma2(ap, B1.y, acc[0][3]);
            ap = pack2(A0.y, A0.y);
            acc[1][0] = ffma2(ap, B0.x, acc[1][0]); acc[1][1] = ffma2(ap, B0.y, acc[1][1]);
            acc[1][2] = ffma2(ap, B1.x, acc[1][2]); acc[1][3] = ffma2(ap, B1.y, acc[1][3]);
            ap = pack2(A0.z, A0.z);
            acc[2][0] = ffma2(ap, B0.x, acc[2][0]); acc[2][1] = ffma2(ap, B0.y, acc[2][1]);
            acc[2][2] = ffma2(ap, B1.x, acc[2][2]); acc[2][3] = ffma2(ap, B1.y, acc[2][3]);
            ap = pack2(A0.w, A0.w);
            acc[3][0] = ffma2(ap, B0.x, acc[3][0]); acc[3][1] = ffma2(ap, B0.y, acc[3][1]);
            acc[3][2] = ffma2(ap, B1.x, acc[3][2]); acc[3][3] = ffma2(ap, B1.y, acc[3][3]);
            ap = pack2(A1.x, A1.x);
            acc[4][0] = ffma2(ap, B0.x, acc[4][0]); acc[4][1] = ffma2(ap, B0.y, acc[4][1]);
            acc[4][2] = ffma2(ap, B1.x, acc[4][2]); acc[4][3] = ffma2(ap, B1.y, acc[4][3]);
            ap = pack2(A1.y, A1.y);
            acc[5][0] = ffma2(ap, B0.x, acc[5][0]); acc[5][1] = ffma2(ap, B0.y, acc[5][1]);
            acc[5][2] = ffma2(ap, B1.x, acc[5][2]); acc[5][3] = ffma2(ap, B1.y, acc[5][3]);
            ap = pack2(A1.z, A1.z);
            acc[6][0] = ffma2(ap, B0.x, acc[6][0]); acc[6][1] = ffma2(ap, B0.y, acc[6][1]);
            acc[6][2] = ffma2(ap, B1.x, acc[6][2]); acc[6][3] = ffma2(ap, B1.y, acc[6][3]);
            ap = pack2(A1.w, A1.w);
            acc[7][0] = ffma2(ap, B0.x, acc[7][0]); acc[7][1] = ffma2(ap, B0.y, acc[7][1]);
            acc[7][2] = ffma2(ap, B1.x, acc[7][2]); acc[7][3] = ffma2(ap, B1.y, acc[7][3]);
        }
        if (c + 1 < nchunk) {
            const int nb = (c + 1) & 1;
#pragma unroll
            for (int i = 0; i < 2; i++) {
                int f4  = i * 256 + tid;
                int row = f4 >> 2;
                int kg  = (f4 & 3) * 4;
                As[nb][kg + 0][row] = la[i].x; As[nb][kg + 1][row] = la[i].y;
                As[nb][kg + 2][row] = la[i].z; As[nb][kg + 3][row] = la[i].w;
                int kr = f4 >> 5;
                int nc = (f4 & 31) * 4;
                *(float4*)&Bs[nb][kr][nc] = lb[i];
            }
            __syncthreads();
        }
    }

#pragma unroll
    for (int i = 0; i < 8; i++) {
        int m = m0 + ty * 8 + i;
#pragma unroll
        for (int p = 0; p < 4; p++) {
            int n = n0 + tx * 8 + p * 2;
            float2 v = unpack2(acc[i][p]);
            v.x += bias[n]; v.y += bias[n + 1];
            if (act) { v.x = tanhf(v.x); v.y = tanhf(v.y); }
            *(float2*)(C + (size_t)m * N + n) = v;
        }
    }
}

// ---------------- persistent BiGRU kernel: full time loop in one launch ---------
// Each block owns SPB sequences; h-state lives in smem across all T steps.
// Weights double-buffer-staged from global (L2-hot) per 16-row chunk.
// dir 1 implements reverse_seq(gru(reverse_seq(x))) via te = len-1-t remapping.
template<int SPB>
__global__ void gru_seq_kernel(
    const float* __restrict__ XWg0, const float* __restrict__ XWg1,
    const float* __restrict__ XWc0, const float* __restrict__ XWc1,
    const float* __restrict__ Wgh0, const float* __restrict__ Wgh1,
    const float* __restrict__ Wch0, const float* __restrict__ Wch1,
    const int*   __restrict__ lens,
    float* __restrict__ outp, int T)
{
    constexpr int SR  = SPB / 4;   // gate: seqs per thread-group row
    constexpr int SRc = SPB / 8;   // candidate: seqs per thread-group row
    const int dir = blockIdx.y;
    const float* XWg = dir ? XWg1 : XWg0;
    const float* XWc = dir ? XWc1 : XWc0;
    const float* Wgh = dir ? Wgh1 : Wgh0;
    const float* Wch = dir ? Wch1 : Wch0;
    const int col_off = dir * CC;

    extern __shared__ float smem[];
    float* sh  = smem;                     // SPB*HH  (h state, persistent)
    float* srh = sh  + SPB * HH;           // SPB*HH  (r*h)
    float* sz  = srh + SPB * HH;           // SPB*HH  (z)
    float* wst = sz  + SPB * HH;           // 2 * 16*GC weight staging
    int*   slen = (int*)(wst + 2 * 16 * GC);

    const int tid = threadIdx.x;
    const int nb  = blockIdx.x * SPB;
    if (tid < SPB) slen[tid] = lens[nb + tid];
    for (int i = tid; i < SPB * HH; i += 256) sh[i] = 0.f;
    __syncthreads();

    const int ct = tid & 63, rt = tid >> 6;
    const int j0 = ct * 4,  s0 = rt * SR;
    const int ctc = tid & 31;
    const int j4 = ctc * 4, s0c = (tid >> 5) * SRc;

    for (int t = 0; t < T; t++) {
        // ============ gate phase: acc = h @ Wgh  (HH x GC) ============
        ull accg[SR][2];
#pragma unroll
        for (int s = 0; s < SR; s++) { accg[s][0] = 0ull; accg[s][1] = 0ull; }

        float4 wl[4];
        {   // stage chunk 0 -> buf 0
            const float4* src = (const float4*)Wgh;
#pragma unroll
            for (int i = 0; i < 4; i++) wl[i] = src[tid + i * 256];
            float4* dst = (float4*)wst;
#pragma unroll
            for (int i = 0; i < 4; i++) dst[tid + i * 256] = wl[i];
        }
        __syncthreads();

        for (int c = 0; c < 8; c++) {
            if (c < 7) {
                const float4* src = (const float4*)(Wgh + (size_t)(c + 1) * 16 * GC);
#pragma unroll
                for (int i = 0; i < 4; i++) wl[i] = src[tid + i * 256];
            }
            const float* wt = wst + (c & 1) * (16 * GC);
            const int kc = c * 16;
#pragma unroll
            for (int k = 0; k < 16; k += 4) {
                ulonglong2 w0 = *(const ulonglong2*)(wt + (k + 0) * GC + j0);
                ulonglong2 w1 = *(const ulonglong2*)(wt + (k + 1) * GC + j0);
                ulonglong2 w2 = *(const ulonglong2*)(wt + (k + 2) * GC + j0);
                ulonglong2 w3 = *(const ulonglong2*)(wt + (k + 3) * GC + j0);
#pragma unroll
                for (int s = 0; s < SR; s++) {
                    float4 hv = *(const float4*)(sh + (s0 + s) * HH + kc + k);
                    ull ap;
                    ap = pack2(hv.x, hv.x);
                    accg[s][0] = ffma2(ap, w0.x, accg[s][0]); accg[s][1] = ffma2(ap, w0.y, accg[s][1]);
                    ap = pack2(hv.y, hv.y);
                    accg[s][0] = ffma2(ap, w1.x, accg[s][0]); accg[s][1] = ffma2(ap, w1.y, accg[s][1]);
                    ap = pack2(hv.z, hv.z);
                    accg[s][0] = ffma2(ap, w2.x, accg[s][0]); accg[s][1] = ffma2(ap, w2.y, accg[s][1]);
                    ap = pack2(hv.w, hv.w);
                    accg[s][0] = ffma2(ap, w3.x, accg[s][0]); accg[s][1] = ffma2(ap, w3.y, accg[s][1]);
                }
            }
            if (c < 7) {
                float4* dst = (float4*)(wst + ((c + 1) & 1) * (16 * GC));
#pragma unroll
                for (int i = 0; i < 4; i++) dst[tid + i * 256] = wl[i];
                __syncthreads();
            }
        }

        // gate epilogue: r,z = sigmoid(acc + XWg); write r*h and z
#pragma unroll
        for (int s = 0; s < SR; s++) {
            int sl = s0 + s;
            int n  = nb + sl;
            int L  = slen[sl];
            int te = dir ? ((t < L) ? (L - 1 - t) : t) : t;
            float4 xg = *(const float4*)(XWg + ((size_t)n * T + te) * GC + j0);
            float2 g01 = unpack2(accg[s][0]);
            float2 g23 = unpack2(accg[s][1]);
            float v0 = 1.f / (1.f + expf(-(g01.x + xg.x)));
            float v1 = 1.f / (1.f + expf(-(g01.y + xg.y)));
            float v2 = 1.f / (1.f + expf(-(g23.x + xg.z)));
            float v3 = 1.f / (1.f + expf(-(g23.y + xg.w)));
            if (ct < 32) {
                float4 hv = *(const float4*)(sh + sl * HH + j0);
                float4 o; o.x = v0 * hv.x; o.y = v1 * hv.y; o.z = v2 * hv.z; o.w = v3 * hv.w;
                *(float4*)(srh + sl * HH + j0) = o;
            } else {
                float4 o; o.x = v0; o.y = v1; o.z = v2; o.w = v3;
                *(float4*)(sz + sl * HH + (j0 - 128)) = o;
            }
        }

        // ============ candidate phase: acc2 = (r*h) @ Wch (HH x CC) ============
        ull accc[SRc][2];
#pragma unroll
        for (int s = 0; s < SRc; s++) { accc[s][0] = 0ull; accc[s][1] = 0ull; }

        float4 wl2[2];
        {   // stage chunk 0 -> buf 0
            const float4* src = (const float4*)Wch;
#pragma unroll
            for (int i = 0; i < 2; i++) wl2[i] = src[tid + i * 256];
            float4* dst = (float4*)wst;
#pragma unroll
            for (int i = 0; i < 2; i++) dst[tid + i * 256] = wl2[i];
        }
        __syncthreads();   // also publishes srh/sz from gate epilogue

        for (int c = 0; c < 8; c++) {
            if (c < 7) {
                const float4* src = (const float4*)(Wch + (size_t)(c + 1) * 16 * CC);
#pragma unroll
                for (int i = 0; i < 2; i++) wl2[i] = src[tid + i * 256];
            }
            const float* wt = wst + (c & 1) * (16 * GC);
            const int kc = c * 16;
#pragma unroll
            for (int k = 0; k < 16; k += 4) {
                ulonglong2 w0 = *(const ulonglong2*)(wt + (k + 0) * CC + j4);
                ulonglong2 w1 = *(const ulonglong2*)(wt + (k + 1) * CC + j4);
                ulonglong2 w2 = *(const ulonglong2*)(wt + (k + 2) * CC + j4);
                ulonglong2 w3 = *(const ulonglong2*)(wt + (k + 3) * CC + j4);
#pragma unroll
                for (int s = 0; s < SRc; s++) {
                    float4 hv = *(const float4*)(srh + (s0c + s) * HH + kc + k);
                    ull ap;
                    ap = pack2(hv.x, hv.x);
                    accc[s][0] = ffma2(ap, w0.x, accc[s][0]); accc[s][1] = ffma2(ap, w0.y, accc[s][1]);
                    ap = pack2(hv.y, hv.y);
                    accc[s][0] = ffma2(ap, w1.x, accc[s][0]); accc[s][1] = ffma2(ap, w1.y, accc[s][1]);
                    ap = pack2(hv.z, hv.z);
                    accc[s][0] = ffma2(ap, w2.x, accc[s][0]); accc[s][1] = ffma2(ap, w2.y, accc[s][1]);
                    ap = pack2(hv.w, hv.w);
                    accc[s][0] = ffma2(ap, w3.x, accc[s][0]); accc[s][1] = ffma2(ap, w3.y, accc[s][1]);
                }
            }
            if (c < 7) {
                float4* dst = (float4*)(wst + ((c + 1) & 1) * (16 * GC));
#pragma unroll
                for (int i = 0; i < 2; i++) dst[tid + i * 256] = wl2[i];
                __syncthreads();
            }
        }

        // final epilogue: c = tanh(acc2 + XWc); h' = z*h + (1-z)*c, masked
#pragma unroll
        for (int s = 0; s < SRc; s++) {
            int sl = s0c + s;
            int n  = nb + sl;
            int L  = slen[sl];
            bool valid = (t < L);
            int te = dir ? (valid ? (L - 1 - t) : t) : t;
            float4 xc = *(const float4*)(XWc + ((size_t)n * T + te) * CC + j4);
            float2 c01 = unpack2(accc[s][0]);
            float2 c23 = unpack2(accc[s][1]);
            float c0 = tanhf(c01.x + xc.x);
            float c1 = tanhf(c01.y + xc.y);
            float c2 = tanhf(c23.x + xc.z);
            float c3 = tanhf(c23.y + xc.w);
            float4 zv = *(const float4*)(sz + sl * HH + j4);
            float4 hv = *(const float4*)(sh + sl * HH + j4);
            float hn0 = zv.x * hv.x + (1.f - zv.x) * c0;
            float hn1 = zv.y * hv.y + (1.f - zv.y) * c1;
            float hn2 = zv.z * hv.z + (1.f - zv.z) * c2;
            float hn3 = zv.w * hv.w + (1.f - zv.w) * c3;
            float4 hw;
            hw.x = valid ? hn0 : hv.x; hw.y = valid ? hn1 : hv.y;
            hw.z = valid ? hn2 : hv.z; hw.w = valid ? hn3 : hv.w;
            *(float4*)(sh + sl * HH + j4) = hw;
            float4 ov;
            ov.x = valid ? hn0 : 0.f; ov.y = valid ? hn1 : 0.f;
            ov.z = valid ? hn2 : 0.f; ov.w = valid ? hn3 : 0.f;
            *(float4*)(outp + ((size_t)n * T + te) * GC + col_off + j4) = ov;
        }
        __syncthreads();   // h-state stable before next step
    }
}

// ---------------- attention: score = proj @ u; softmax over T; vec = att @ seq ----
__global__ void attention_kernel(const float* __restrict__ proj,  // [N*T*128]
                                 const float* __restrict__ u,     // [128]
                                 const float* __restrict__ seq,   // [N*T*256]
                                 float* __restrict__ vec,         // [N*256]
                                 float* __restrict__ att_out,     // [N*T]
                                 int N, int T)
{
    const int n = blockIdx.x;
    const int tid = threadIdx.x;
    const int warp = tid >> 5, lane = tid & 31;
    __shared__ float su[128];
    __shared__ float sc[64];
    __shared__ float red[2];
    if (tid < 128) su[tid] = u[tid];
    __syncthreads();

    for (int t = warp; t < T; t += 8) {
        const float* pr = proj + ((size_t)n * T + t) * 128;
        float p = 0.f;
#pragma unroll
        for (int i = 0; i < 4; i++) p += pr[lane + i * 32] * su[lane + i * 32];
#pragma unroll
        for (int o = 16; o > 0; o >>= 1) p += __shfl_xor_sync(0xffffffffu, p, o);
        if (lane == 0) sc[t] = p;
    }
    __syncthreads();
    if (tid == 0) {
        float m = sc[0];
        for (int t = 1; t < T; t++) m = fmaxf(m, sc[t]);
        float s = 0.f;
        for (int t = 0; t < T; t++) s += expf(sc[t] - m);
        red[0] = m; red[1] = s;
    }
    __syncthreads();
    if (tid < T) {
        float a = expf(sc[tid] - red[0]) / red[1];
        att_out[(size_t)n * T + tid] = a;
        sc[tid] = a;
    }
    __syncthreads();
    {
        int c = tid;
        float a = 0.f;
        for (int t = 0; t < T; t++) a += sc[t] * seq[((size_t)n * T + t) * 256 + c];
        vec[(size_t)n * 256 + c] = a;
    }
}

// ---------------- final: logits, log-softmax, loss, reg, predict, accuracy -------
__global__ void final_kernel(const float* __restrict__ docvec, const float* __restrict__ wp,
                             const float* __restrict__ bp, const int* __restrict__ y,
                             const float* __restrict__ wa_l, const float* __restrict__ ba_l,
                             const float* __restrict__ wa_h, const float* __restrict__ uw,
                             const float* __restrict__ us, float* __restrict__ out)
{
    __shared__ float slog[640];
    __shared__ float red[256];
    __shared__ float lossb[64];
    __shared__ int corr[64];
    const int tid = threadIdx.x;

    for (int idx = tid; idx < 640; idx += 256) {
        int b = idx / 10, c = idx % 10;
        float a = bp[c];
        for (int k = 0; k < 256; k++) a += docvec[b * 256 + k] * wp[k * 10 + c];
        slog[idx] = a;
    }
    __syncthreads();
    if (tid < 64) {
        int b = tid;
        float m = slog[b * 10]; int am = 0;
        for (int c = 1; c < 10; c++) { float v = slog[b * 10 + c]; if (v > m) { m = v; am = c; } }
        float s = 0.f;
        for (int c = 0; c < 10; c++) s += expf(slog[b * 10 + c] - m);
        float lse = m + logf(s);
        int yb = y[b];
        lossb[b] = lse - slog[b * 10 + yb];
        corr[b]  = (am == yb) ? 1 : 0;
        out[1 + b] = (float)am;
    }
    float r = 0.f;
    for (int i = tid; i < 256 * 128; i += 256) {
        float v = wa_l[i]; r += v * v;
        float w = wa_h[i]; r += 2.f * w * w;
    }
    for (int i = tid; i < 128; i += 256) {
        float v = ba_l[i]; r += v * v;
        float a = uw[i];   r += a * a;
        float b2 = us[i];  r += b2 * b2;
    }
    red[tid] = r;
    __syncthreads();
    for (int o = 128; o > 0; o >>= 1) { if (tid < o) red[tid] += red[tid + o]; __syncthreads(); }
    if (tid == 0) {
        float L = 0.f; int C = 0;
        for (int b = 0; b < 64; b++) { L += lossb[b]; C += corr[b]; }
        out[0]  = L / 64.f + 0.01f * red[0];
        out[65] = (float)C / 64.f;
    }
}

// =================================================================================
extern "C" void kernel_launch(void* const* d_in, const int* in_sizes, int n_in,
                              void* d_out, int out_size)
{
    (void)in_sizes; (void)out_size;
    const float* X    = (const float*)d_in[0];
    const int*   y    = (const int*)d_in[1];
    const int*   slen = (const int*)d_in[2];
    const int*   dlen = (const int*)d_in[3];
    const int wo = (n_in >= 30) ? 6 : (n_in - 24);
    const float* Wt[24];
    for (int i = 0; i < 24; i++) Wt[i] = (const float*)d_in[wo + i];
    const float *wgf_l = Wt[0],  *bgf_l = Wt[1],  *wcf_l = Wt[2],  *bcf_l = Wt[3];
    const float *wgb_l = Wt[4],  *bgb_l = Wt[5],  *wcb_l = Wt[6],  *bcb_l = Wt[7];
    const float *wa_l  = Wt[8],  *ba_l  = Wt[9];
    const float *wgf_h = Wt[10], *bgf_h = Wt[11], *wcf_h = Wt[12], *bcf_h = Wt[13];
    const float *wgb_h = Wt[14], *bgb_h = Wt[15], *wcb_h = Wt[16], *bcb_h = Wt[17];
    const float *wa_h  = Wt[18], *ba_h  = Wt[19];
    const float *uw = Wt[20], *us = Wt[21], *wp = Wt[22], *bp = Wt[23];
    float* out = (float*)d_out;

    float *XWg_f, *XWc_f, *XWg_b, *XWc_b, *low, *proj, *sent;
    float *sXWg_f, *sXWc_f, *sXWg_b, *sXWc_b, *high, *docvec;
    cudaGetSymbolAddress((void**)&XWg_f, g_XWg_f);
    cudaGetSymbolAddress((void**)&XWc_f, g_XWc_f);
    cudaGetSymbolAddress((void**)&XWg_b, g_XWg_b);
    cudaGetSymbolAddress((void**)&XWc_b, g_XWc_b);
    cudaGetSymbolAddress((void**)&low,   g_low);
    cudaGetSymbolAddress((void**)&proj,  g_proj);
    cudaGetSymbolAddress((void**)&sent,  g_sent);
    cudaGetSymbolAddress((void**)&sXWg_f, g_sXWg_f);
    cudaGetSymbolAddress((void**)&sXWc_f, g_sXWc_f);
    cudaGetSymbolAddress((void**)&sXWg_b, g_sXWg_b);
    cudaGetSymbolAddress((void**)&sXWc_b, g_sXWc_b);
    cudaGetSymbolAddress((void**)&high,  g_high);
    cudaGetSymbolAddress((void**)&docvec, g_docvec);

    const int smem16 = (3 * 16 * HH + 2 * 16 * GC) * 4 + 16 * 4;   // ~57.4 KB
    const int smem8  = (3 * 8  * HH + 2 * 16 * GC) * 4 + 8 * 4;    // ~45 KB
    cudaFuncSetAttribute(gru_seq_kernel<16>, cudaFuncAttributeMaxDynamicSharedMemorySize, smem16);
    cudaFuncSetAttribute(gru_seq_kernel<8>,  cudaFuncAttributeMaxDynamicSharedMemorySize, smem8);

    // 1) word-level input precompute: x @ W_x + b
    sgemm_bias<<<dim3(BD * SW / 128, 2), 256>>>(X, wgf_l, bgf_l, XWg_f, BD * SW, GC, EW, 0);
    sgemm_bias<<<dim3(BD * SW / 128, 1), 256>>>(X, wcf_l, bcf_l, XWc_f, BD * SW, CC, EW, 0);
    sgemm_bias<<<dim3(BD * SW / 128, 2), 256>>>(X, wgb_l, bgb_l, XWg_b, BD * SW, GC, EW, 0);
    sgemm_bias<<<dim3(BD * SW / 128, 1), 256>>>(X, wcb_l, bcb_l, XWc_b, BD * SW, CC, EW, 0);

    // 2) word-level BiGRU: entire 50-step recurrence, one launch
    gru_seq_kernel<16><<<dim3(BD / 16, 2), 256, smem16>>>(
        XWg_f, XWg_b, XWc_f, XWc_b,
        wgf_l + (size_t)EW * GC, wgb_l + (size_t)EW * GC,
        wcf_l + (size_t)EW * CC, wcb_l + (size_t)EW * CC,
        slen, low, SW);

    // 3) word attention
    sgemm_bias<<<dim3(BD * SW / 128, 1), 256>>>(low, wa_l, ba_l, proj, BD * SW, CC, GC, 1);
    attention_kernel<<<BD, 256>>>(proj, uw, low, sent, out + 66, BD, SW);

    // 4) sentence-level input precompute
    sgemm_bias<<<dim3(BB * DD / 128, 2), 256>>>(sent, wgf_h, bgf_h, sXWg_f, BB * DD, GC, GC, 0);
    sgemm_bias<<<dim3(BB * DD / 128, 1), 256>>>(sent, wcf_h, bcf_h, sXWc_f, BB * DD, CC, GC, 0);
    sgemm_bias<<<dim3(BB * DD / 128, 2), 256>>>(sent, wgb_h, bgb_h, sXWg_b, BB * DD, GC, GC, 0);
    sgemm_bias<<<dim3(BB * DD / 128, 1), 256>>>(sent, wcb_h, bcb_h, sXWc_b, BB * DD, CC, GC, 0);

    // 5) sentence-level BiGRU: entire 40-step recurrence, one launch
    gru_seq_kernel<8><<<dim3(BB / 8, 2), 256, smem8>>>(
        sXWg_f, sXWg_b, sXWc_f, sXWc_b,
        wgf_h + (size_t)GC * GC, wgb_h + (size_t)GC * GC,
        wcf_h + (size_t)GC * CC, wcb_h + (size_t)GC * CC,
        dlen, high, DD);

    // 6) sentence attention
    sgemm_bias<<<dim3(BB * DD / 128, 1), 256>>>(high, wa_h, ba_h, proj, BB * DD, CC, GC, 1);
    attention_kernel<<<BB, 256>>>(proj, us, high, docvec, out + 66 + BD * SW, BB, DD);

    // 7) classifier / loss / reg / predict / accuracy
    final_kernel<<<1, 256>>>(docvec, wp, bp, y, wa_l, ba_l, wa_h, uw, us, out);
}

// round 6
// speedup vs baseline: 1.5039x; 1.2415x over previous
#include <cuda_runtime.h>
#include <math.h>
#include <stdint.h>
#include <stddef.h>

// Problem dims (fixed by the dataset)
#define BD   2560      // B*D word-level sequences
#define SW   50        // word-level T
#define EW   200       // embedding
#define HH   128       // GRU hidden
#define BB   64        // batch (docs)
#define DD   40        // sentences per doc
#define GC   256       // gate cols = 2H (also bigru output width)
#define CC   128       // candidate cols = H

typedef unsigned long long ull;

// ---------------- packed fp32x2 helpers (sm_103a FFMA2 path) ----------------
__device__ __forceinline__ ull ffma2(ull a, ull b, ull c) {
    ull d;
    asm("fma.rn.f32x2 %0, %1, %2, %3;" : "=l"(d) : "l"(a), "l"(b), "l"(c));
    return d;
}
__device__ __forceinline__ ull pack2(float x, float y) {
    ull d;
    asm("mov.b64 %0, {%1, %2};" : "=l"(d) : "r"(__float_as_uint(x)), "r"(__float_as_uint(y)));
    return d;
}
__device__ __forceinline__ float2 unpack2(ull v) {
    unsigned lo, hi;
    asm("mov.b64 {%0, %1}, %2;" : "=r"(lo), "=r"(hi) : "l"(v));
    float2 r; r.x = __uint_as_float(lo); r.y = __uint_as_float(hi);
    return r;
}

// ---------------- scratch (device globals; no allocation allowed) ----------------
__device__ float g_XWg_f[(size_t)BD*SW*GC];
__device__ float g_XWc_f[(size_t)BD*SW*CC];
__device__ float g_XWg_b[(size_t)BD*SW*GC];
__device__ float g_XWc_b[(size_t)BD*SW*CC];
__device__ float g_low  [(size_t)BD*SW*GC];
__device__ float g_proj [(size_t)BD*SW*CC];
__device__ float g_sent[BD*GC];
__device__ float g_sXWg_f[BB*DD*GC];
__device__ float g_sXWc_f[BB*DD*CC];
__device__ float g_sXWg_b[BB*DD*GC];
__device__ float g_sXWc_b[BB*DD*CC];
__device__ float g_high[BB*DD*GC];
__device__ float g_docvec[BB*GC];

// ---------------- generic fp32 GEMM: C = A[MxK] @ W[KxN] + bias, optional tanh ----
// 128x128 tile, FFMA2 inner product, double-buffered smem, 2 CTAs/SM forced.
__global__ void __launch_bounds__(256, 2)
sgemm_bias(const float* __restrict__ A, const float* __restrict__ W,
           const float* __restrict__ bias, float* __restrict__ C,
           int M, int N, int K, int act)
{
    __shared__ __align__(16) float As[2][16][128];
    __shared__ __align__(16) float Bs[2][16][128];
    const int tid = threadIdx.x;
    const int m0 = blockIdx.x * 128;
    const int n0 = blockIdx.y * 128;
    const int tx = tid & 15;
    const int ty = tid >> 4;

    ull acc[8][4];
#pragma unroll
    for (int i = 0; i < 8; i++)
#pragma unroll
        for (int j = 0; j < 4; j++) acc[i][j] = 0ull;

    const int nchunk = (K + 15) / 16;
    float4 la[2], lb[2];

#pragma unroll
    for (int i = 0; i < 2; i++) {
        int f4  = i * 256 + tid;
        int row = f4 >> 2;
        int kg  = (f4 & 3) * 4;
        la[i] = make_float4(0.f, 0.f, 0.f, 0.f);
        if (kg < K) la[i] = *(const float4*)(A + (size_t)(m0 + row) * K + kg);
        int kr = f4 >> 5;
        int nc = (f4 & 31) * 4;
        lb[i] = make_float4(0.f, 0.f, 0.f, 0.f);
        if (kr < K) lb[i] = *(const float4*)(W + (size_t)kr * N + n0 + nc);
    }
#pragma unroll
    for (int i = 0; i < 2; i++) {
        int f4  = i * 256 + tid;
        int row = f4 >> 2;
        int kg  = (f4 & 3) * 4;
        As[0][kg + 0][row] = la[i].x; As[0][kg + 1][row] = la[i].y;
        As[0][kg + 2][row] = la[i].z; As[0][kg + 3][row] = la[i].w;
        int kr = f4 >> 5;
        int nc = (f4 & 31) * 4;
        *(float4*)&Bs[0][kr][nc] = lb[i];
    }
    __syncthreads();

    for (int c = 0; c < nchunk; c++) {
        if (c + 1 < nchunk) {
            const int k0 = (c + 1) * 16;
#pragma unroll
            for (int i = 0; i < 2; i++) {
                int f4  = i * 256 + tid;
                int row = f4 >> 2;
                int kg  = (f4 & 3) * 4;
                la[i] = make_float4(0.f, 0.f, 0.f, 0.f);
                if (k0 + kg < K) la[i] = *(const float4*)(A + (size_t)(m0 + row) * K + k0 + kg);
                int kr = f4 >> 5;
                int nc = (f4 & 31) * 4;
                lb[i] = make_float4(0.f, 0.f, 0.f, 0.f);
                if (k0 + kr < K) lb[i] = *(const float4*)(W + (size_t)(k0 + kr) * N + n0 + nc);
            }
        }
        const int cb = c & 1;
#pragma unroll
        for (int k = 0; k < 16; k++) {
            float4 A0 = *(const float4*)&As[cb][k][ty * 8];
            float4 A1 = *(const float4*)&As[cb][k][ty * 8 + 4];
            ulonglong2 B0 = *(const ulonglong2*)&Bs[cb][k][tx * 8];
            ulonglong2 B1 = *(const ulonglong2*)&Bs[cb][k][tx * 8 + 4];
            ull ap;
            ap = pack2(A0.x, A0.x);
            acc[0][0] = ffma2(ap, B0.x, acc[0][0]); acc[0][1] = ffma2(ap, B0.y, acc[0][1]);
            acc[0][2] = ffma2(ap, B1.x, acc[0][2]); acc[0][3] = ffma2(ap, B1.y, acc[0][3]);
            ap = pack2(A0.y, A0.y);
            acc[1][0] = ffma2(ap, B0.x, acc[1][0]); acc[1][1] = ffma2(ap, B0.y, acc[1][1]);
            acc[1][2] = ffma2(ap, B1.x, acc[1][2]); acc[1][3] = ffma2(ap, B1.y, acc[1][3]);
            ap = pack2(A0.z, A0.z);
            acc[2][0] = ffma2(ap, B0.x, acc[2][0]); acc[2][1] = ffma2(ap, B0.y, acc[2][1]);
            acc[2][2] = ffma2(ap, B1.x, acc[2][2]); acc[2][3] = ffma2(ap, B1.y, acc[2][3]);
            ap = pack2(A0.w, A0.w);
            acc[3][0] = ffma2(ap, B0.x, acc[3][0]); acc[3][1] = ffma2(ap, B0.y, acc[3][1]);
            acc[3][2] = ffma2(ap, B1.x, acc[3][2]); acc[3][3] = ffma2(ap, B1.y, acc[3][3]);
            ap = pack2(A1.x, A1.x);
            acc[4][0] = ffma2(ap, B0.x, acc[4][0]); acc[4][1] = ffma2(ap, B0.y, acc[4][1]);
            acc[4][2] = ffma2(ap, B1.x, acc[4][2]); acc[4][3] = ffma2(ap, B1.y, acc[4][3]);
            ap = pack2(A1.y, A1.y);
            acc[5][0] = ffma2(ap, B0.x, acc[5][0]); acc[5][1] = ffma2(ap, B0.y, acc[5][1]);
            acc[5][2] = ffma2(ap, B1.x, acc[5][2]); acc[5][3] = ffma2(ap, B1.y, acc[5][3]);
            ap = pack2(A1.z, A1.z);
            acc[6][0] = ffma2(ap, B0.x, acc[6][0]); acc[6][1] = ffma2(ap, B0.y, acc[6][1]);
            acc[6][2] = ffma2(ap, B1.x, acc[6][2]); acc[6][3] = ffma2(ap, B1.y, acc[6][3]);
            ap = pack2(A1.w, A1.w);
            acc[7][0] = ffma2(ap, B0.x, acc[7][0]); acc[7][1] = ffma2(ap, B0.y, acc[7][1]);
            acc[7][2] = ffma2(ap, B1.x, acc[7][2]); acc[7][3] = ffma2(ap, B1.y, acc[7][3]);
        }
        if (c + 1 < nchunk) {
            const int nb = (c + 1) & 1;
#pragma unroll
            for (int i = 0; i < 2; i++) {
                int f4  = i * 256 + tid;
                int row = f4 >> 2;
                int kg  = (f4 & 3) * 4;
                As[nb][kg + 0][row] = la[i].x; As[nb][kg + 1][row] = la[i].y;
                As[nb][kg + 2][row] = la[i].z; As[nb][kg + 3][row] = la[i].w;
                int kr = f4 >> 5;
                int nc = (f4 & 31) * 4;
                *(float4*)&Bs[nb][kr][nc] = lb[i];
            }
            __syncthreads();
        }
    }

#pragma unroll
    for (int i = 0; i < 8; i++) {
        int m = m0 + ty * 8 + i;
#pragma unroll
        for (int p = 0; p < 4; p++) {
            int n = n0 + tx * 8 + p * 2;
            float2 v = unpack2(acc[i][p]);
            v.x += bias[n]; v.y += bias[n + 1];
            if (act) { v.x = tanhf(v.x); v.y = tanhf(v.y); }
            *(float2*)(C + (size_t)m * N + n) = v;
        }
    }
}

// ---------------- resident-weight BiGRU kernel -----------------------------------
// Weights (Wgh 128KB + Wch 64KB) loaded ONCE into smem; h/rh/z state also in smem.
// Whole T loop in one launch, 2 syncs per step, zero per-step weight traffic.
// dir=blockIdx.y; bw implements reverse_seq(gru(reverse_seq(x))) via te=len-1-t.
// 256 threads; SPB sequences per block, SPB % 4 == 0 (SR = SPB/4 seqs per row-group).
template<int SPB>
__global__ void __launch_bounds__(256, 1)
gru_resident_kernel(
    const float* __restrict__ XWg0, const float* __restrict__ XWg1,
    const float* __restrict__ XWc0, const float* __restrict__ XWc1,
    const float* __restrict__ Wgh0, const float* __restrict__ Wgh1,
    const float* __restrict__ Wch0, const float* __restrict__ Wch1,
    const int*   __restrict__ lens,
    float* __restrict__ outp, int T)
{
    constexpr int SR = SPB / 4;
    const int dir = blockIdx.y;
    const float* XWg = dir ? XWg1 : XWg0;
    const float* XWc = dir ? XWc1 : XWc0;
    const float* Wgh = dir ? Wgh1 : Wgh0;
    const float* Wch = dir ? Wch1 : Wch0;
    const int col_off = dir * CC;

    extern __shared__ float smem[];
    float* swg = smem;                    // HH*GC = 32768 floats (128KB)
    float* swc = swg + HH * GC;           // HH*CC = 16384 floats (64KB)
    float* sh  = swc + HH * CC;           // SPB*HH
    float* srh = sh  + SPB * HH;
    float* sz  = srh + SPB * HH;
    int*   slen = (int*)(sz + SPB * HH);

    const int tid = threadIdx.x;
    const int nb  = blockIdx.x * SPB;
    if (tid < SPB) slen[tid] = lens[nb + tid];

    // ---- load weights once ----
    {
        const float4* src = (const float4*)Wgh;
        float4* dst = (float4*)swg;
        for (int i = tid; i < HH * GC / 4; i += 256) dst[i] = src[i];
        src = (const float4*)Wch;
        dst = (float4*)swc;
        for (int i = tid; i < HH * CC / 4; i += 256) dst[i] = src[i];
    }
    for (int i = tid; i < SPB * HH; i += 256) sh[i] = 0.f;
    __syncthreads();

    const int ct = tid & 63, rt = tid >> 6;
    const int j0 = ct * 4;    // gate cols (4 per thread, 256 total)
    const int j2 = ct * 2;    // candidate cols (2 per thread, 128 total)
    const int s0 = rt * SR;

    for (int t = 0; t < T; t++) {
        // ===== gate: acc = h @ Wgh (weights in smem) =====
        ull accg[SR][2];
#pragma unroll
        for (int s = 0; s < SR; s++) { accg[s][0] = 0ull; accg[s][1] = 0ull; }

#pragma unroll 4
        for (int kc = 0; kc < HH; kc += 4) {
            ulonglong2 w0 = *(const ulonglong2*)(swg + (size_t)(kc + 0) * GC + j0);
            ulonglong2 w1 = *(const ulonglong2*)(swg + (size_t)(kc + 1) * GC + j0);
            ulonglong2 w2 = *(const ulonglong2*)(swg + (size_t)(kc + 2) * GC + j0);
            ulonglong2 w3 = *(const ulonglong2*)(swg + (size_t)(kc + 3) * GC + j0);
#pragma unroll
            for (int s = 0; s < SR; s++) {
                float4 hv = *(const float4*)(sh + (s0 + s) * HH + kc);
                ull ap;
                ap = pack2(hv.x, hv.x);
                accg[s][0] = ffma2(ap, w0.x, accg[s][0]); accg[s][1] = ffma2(ap, w0.y, accg[s][1]);
                ap = pack2(hv.y, hv.y);
                accg[s][0] = ffma2(ap, w1.x, accg[s][0]); accg[s][1] = ffma2(ap, w1.y, accg[s][1]);
                ap = pack2(hv.z, hv.z);
                accg[s][0] = ffma2(ap, w2.x, accg[s][0]); accg[s][1] = ffma2(ap, w2.y, accg[s][1]);
                ap = pack2(hv.w, hv.w);
                accg[s][0] = ffma2(ap, w3.x, accg[s][0]); accg[s][1] = ffma2(ap, w3.y, accg[s][1]);
            }
        }

        // gate epilogue: r,z = sigmoid(acc + XWg); write r*h (ct<32) / z (ct>=32)
#pragma unroll
        for (int s = 0; s < SR; s++) {
            int sl = s0 + s;
            int n  = nb + sl;
            int L  = slen[sl];
            int te = dir ? ((t < L) ? (L - 1 - t) : t) : t;
            float4 xg = *(const float4*)(XWg + ((size_t)n * T + te) * GC + j0);
            float2 g01 = unpack2(accg[s][0]);
            float2 g23 = unpack2(accg[s][1]);
            float v0 = 1.f / (1.f + expf(-(g01.x + xg.x)));
            float v1 = 1.f / (1.f + expf(-(g01.y + xg.y)));
            float v2 = 1.f / (1.f + expf(-(g23.x + xg.z)));
            float v3 = 1.f / (1.f + expf(-(g23.y + xg.w)));
            if (ct < 32) {
                float4 hv = *(const float4*)(sh + sl * HH + j0);
                float4 o; o.x = v0 * hv.x; o.y = v1 * hv.y; o.z = v2 * hv.z; o.w = v3 * hv.w;
                *(float4*)(srh + sl * HH + j0) = o;
            } else {
                float4 o; o.x = v0; o.y = v1; o.z = v2; o.w = v3;
                *(float4*)(sz + sl * HH + (j0 - 128)) = o;
            }
        }
        __syncthreads();   // srh/sz visible

        // ===== candidate: acc2 = (r*h) @ Wch =====
        ull accc[SR];
#pragma unroll
        for (int s = 0; s < SR; s++) accc[s] = 0ull;

#pragma unroll 4
        for (int kc = 0; kc < HH; kc += 4) {
            ull w0 = *(const ull*)(swc + (size_t)(kc + 0) * CC + j2);
            ull w1 = *(const ull*)(swc + (size_t)(kc + 1) * CC + j2);
            ull w2 = *(const ull*)(swc + (size_t)(kc + 2) * CC + j2);
            ull w3 = *(const ull*)(swc + (size_t)(kc + 3) * CC + j2);
#pragma unroll
            for (int s = 0; s < SR; s++) {
                float4 hv = *(const float4*)(srh + (s0 + s) * HH + kc);
                accc[s] = ffma2(pack2(hv.x, hv.x), w0, accc[s]);
                accc[s] = ffma2(pack2(hv.y, hv.y), w1, accc[s]);
                accc[s] = ffma2(pack2(hv.z, hv.z), w2, accc[s]);
                accc[s] = ffma2(pack2(hv.w, hv.w), w3, accc[s]);
            }
        }

        // final epilogue: c = tanh(acc2 + XWc); h' = z*h + (1-z)*c, masked
#pragma unroll
        for (int s = 0; s < SR; s++) {
            int sl = s0 + s;
            int n  = nb + sl;
            int L  = slen[sl];
            bool valid = (t < L);
            int te = dir ? (valid ? (L - 1 - t) : t) : t;
            float2 xc = *(const float2*)(XWc + ((size_t)n * T + te) * CC + j2);
            float2 cc = unpack2(accc[s]);
            float c0 = tanhf(cc.x + xc.x);
            float c1 = tanhf(cc.y + xc.y);
            float z0 = sz[sl * HH + j2], z1 = sz[sl * HH + j2 + 1];
            float h0 = sh[sl * HH + j2], h1 = sh[sl * HH + j2 + 1];
            float hn0 = z0 * h0 + (1.f - z0) * c0;
            float hn1 = z1 * h1 + (1.f - z1) * c1;
            float2 hw; hw.x = valid ? hn0 : h0; hw.y = valid ? hn1 : h1;
            *(float2*)(sh + sl * HH + j2) = hw;
            float2 ov; ov.x = valid ? hn0 : 0.f; ov.y = valid ? hn1 : 0.f;
            *(float2*)(outp + ((size_t)n * T + te) * GC + col_off + j2) = ov;
        }
        __syncthreads();   // h-state stable before next step
    }
}

// ---------------- attention: score = proj @ u; softmax over T; vec = att @ seq ----
__global__ void attention_kernel(const float* __restrict__ proj,  // [N*T*128]
                                 const float* __restrict__ u,     // [128]
                                 const float* __restrict__ seq,   // [N*T*256]
                                 float* __restrict__ vec,         // [N*256]
                                 float* __restrict__ att_out,     // [N*T]
                                 int N, int T)
{
    const int n = blockIdx.x;
    const int tid = threadIdx.x;
    const int warp = tid >> 5, lane = tid & 31;
    __shared__ float su[128];
    __shared__ float sc[64];
    __shared__ float red[2];
    if (tid < 128) su[tid] = u[tid];
    __syncthreads();

    for (int t = warp; t < T; t += 8) {
        const float* pr = proj + ((size_t)n * T + t) * 128;
        float p = 0.f;
#pragma unroll
        for (int i = 0; i < 4; i++) p += pr[lane + i * 32] * su[lane + i * 32];
#pragma unroll
        for (int o = 16; o > 0; o >>= 1) p += __shfl_xor_sync(0xffffffffu, p, o);
        if (lane == 0) sc[t] = p;
    }
    __syncthreads();
    if (tid == 0) {
        float m = sc[0];
        for (int t = 1; t < T; t++) m = fmaxf(m, sc[t]);
        float s = 0.f;
        for (int t = 0; t < T; t++) s += expf(sc[t] - m);
        red[0] = m; red[1] = s;
    }
    __syncthreads();
    if (tid < T) {
        float a = expf(sc[tid] - red[0]) / red[1];
        att_out[(size_t)n * T + tid] = a;
        sc[tid] = a;
    }
    __syncthreads();
    {
        int c = tid;
        float a = 0.f;
        for (int t = 0; t < T; t++) a += sc[t] * seq[((size_t)n * T + t) * 256 + c];
        vec[(size_t)n * 256 + c] = a;
    }
}

// ---------------- final: logits, log-softmax, loss, reg, predict, accuracy -------
__global__ void final_kernel(const float* __restrict__ docvec, const float* __restrict__ wp,
                             const float* __restrict__ bp, const int* __restrict__ y,
                             const float* __restrict__ wa_l, const float* __restrict__ ba_l,
                             const float* __restrict__ wa_h, const float* __restrict__ uw,
                             const float* __restrict__ us, float* __restrict__ out)
{
    __shared__ float slog[640];
    __shared__ float red[256];
    __shared__ float lossb[64];
    __shared__ int corr[64];
    const int tid = threadIdx.x;

    for (int idx = tid; idx < 640; idx += 256) {
        int b = idx / 10, c = idx % 10;
        float a = bp[c];
        for (int k = 0; k < 256; k++) a += docvec[b * 256 + k] * wp[k * 10 + c];
        slog[idx] = a;
    }
    __syncthreads();
    if (tid < 64) {
        int b = tid;
        float m = slog[b * 10]; int am = 0;
        for (int c = 1; c < 10; c++) { float v = slog[b * 10 + c]; if (v > m) { m = v; am = c; } }
        float s = 0.f;
        for (int c = 0; c < 10; c++) s += expf(slog[b * 10 + c] - m);
        float lse = m + logf(s);
        int yb = y[b];
        lossb[b] = lse - slog[b * 10 + yb];
        corr[b]  = (am == yb) ? 1 : 0;
        out[1 + b] = (float)am;
    }
    float r = 0.f;
    for (int i = tid; i < 256 * 128; i += 256) {
        float v = wa_l[i]; r += v * v;
        float w = wa_h[i]; r += 2.f * w * w;
    }
    for (int i = tid; i < 128; i += 256) {
        float v = ba_l[i]; r += v * v;
        float a = uw[i];   r += a * a;
        float b2 = us[i];  r += b2 * b2;
    }
    red[tid] = r;
    __syncthreads();
    for (int o = 128; o > 0; o >>= 1) { if (tid < o) red[tid] += red[tid + o]; __syncthreads(); }
    if (tid == 0) {
        float L = 0.f; int C = 0;
        for (int b = 0; b < 64; b++) { L += lossb[b]; C += corr[b]; }
        out[0]  = L / 64.f + 0.01f * red[0];
        out[65] = (float)C / 64.f;
    }
}

// =================================================================================
extern "C" void kernel_launch(void* const* d_in, const int* in_sizes, int n_in,
                              void* d_out, int out_size)
{
    (void)in_sizes; (void)out_size;
    const float* X    = (const float*)d_in[0];
    const int*   y    = (const int*)d_in[1];
    const int*   slen = (const int*)d_in[2];
    const int*   dlen = (const int*)d_in[3];
    const int wo = (n_in >= 30) ? 6 : (n_in - 24);
    const float* Wt[24];
    for (int i = 0; i < 24; i++) Wt[i] = (const float*)d_in[wo + i];
    const float *wgf_l = Wt[0],  *bgf_l = Wt[1],  *wcf_l = Wt[2],  *bcf_l = Wt[3];
    const float *wgb_l = Wt[4],  *bgb_l = Wt[5],  *wcb_l = Wt[6],  *bcb_l = Wt[7];
    const float *wa_l  = Wt[8],  *ba_l  = Wt[9];
    const float *wgf_h = Wt[10], *bgf_h = Wt[11], *wcf_h = Wt[12], *bcf_h = Wt[13];
    const float *wgb_h = Wt[14], *bgb_h = Wt[15], *wcb_h = Wt[16], *bcb_h = Wt[17];
    const float *wa_h  = Wt[18], *ba_h  = Wt[19];
    const float *uw = Wt[20], *us = Wt[21], *wp = Wt[22], *bp = Wt[23];
    float* out = (float*)d_out;

    float *XWg_f, *XWc_f, *XWg_b, *XWc_b, *low, *proj, *sent;
    float *sXWg_f, *sXWc_f, *sXWg_b, *sXWc_b, *high, *docvec;
    cudaGetSymbolAddress((void**)&XWg_f, g_XWg_f);
    cudaGetSymbolAddress((void**)&XWc_f, g_XWc_f);
    cudaGetSymbolAddress((void**)&XWg_b, g_XWg_b);
    cudaGetSymbolAddress((void**)&XWc_b, g_XWc_b);
    cudaGetSymbolAddress((void**)&low,   g_low);
    cudaGetSymbolAddress((void**)&proj,  g_proj);
    cudaGetSymbolAddress((void**)&sent,  g_sent);
    cudaGetSymbolAddress((void**)&sXWg_f, g_sXWg_f);
    cudaGetSymbolAddress((void**)&sXWc_f, g_sXWc_f);
    cudaGetSymbolAddress((void**)&sXWg_b, g_sXWg_b);
    cudaGetSymbolAddress((void**)&sXWc_b, g_sXWc_b);
    cudaGetSymbolAddress((void**)&high,  g_high);
    cudaGetSymbolAddress((void**)&docvec, g_docvec);

    // dynamic smem: weights (48K floats) + 3*SPB*HH state + SPB ints
    const int smem_w = (HH * GC + HH * CC + 3 * 20 * HH) * 4 + 20 * 4;  // 227,408 B
    const int smem_s = (HH * GC + HH * CC + 3 * 4  * HH) * 4 + 4 * 4;   // 202,768 B
    cudaFuncSetAttribute(gru_resident_kernel<20>, cudaFuncAttributeMaxDynamicSharedMemorySize, smem_w);
    cudaFuncSetAttribute(gru_resident_kernel<4>,  cudaFuncAttributeMaxDynamicSharedMemorySize, smem_s);

    // 1) word-level input precompute: x @ W_x + b
    sgemm_bias<<<dim3(BD * SW / 128, 2), 256>>>(X, wgf_l, bgf_l, XWg_f, BD * SW, GC, EW, 0);
    sgemm_bias<<<dim3(BD * SW / 128, 1), 256>>>(X, wcf_l, bcf_l, XWc_f, BD * SW, CC, EW, 0);
    sgemm_bias<<<dim3(BD * SW / 128, 2), 256>>>(X, wgb_l, bgb_l, XWg_b, BD * SW, GC, EW, 0);
    sgemm_bias<<<dim3(BD * SW / 128, 1), 256>>>(X, wcb_l, bcb_l, XWc_b, BD * SW, CC, EW, 0);

    // 2) word-level BiGRU: resident weights, 50-step loop, one launch
    gru_resident_kernel<20><<<dim3(BD / 20, 2), 256, smem_w>>>(
        XWg_f, XWg_b, XWc_f, XWc_b,
        wgf_l + (size_t)EW * GC, wgb_l + (size_t)EW * GC,
        wcf_l + (size_t)EW * CC, wcb_l + (size_t)EW * CC,
        slen, low, SW);

    // 3) word attention
    sgemm_bias<<<dim3(BD * SW / 128, 1), 256>>>(low, wa_l, ba_l, proj, BD * SW, CC, GC, 1);
    attention_kernel<<<BD, 256>>>(proj, uw, low, sent, out + 66, BD, SW);

    // 4) sentence-level input precompute
    sgemm_bias<<<dim3(BB * DD / 128, 2), 256>>>(sent, wgf_h, bgf_h, sXWg_f, BB * DD, GC, GC, 0);
    sgemm_bias<<<dim3(BB * DD / 128, 1), 256>>>(sent, wcf_h, bcf_h, sXWc_f, BB * DD, CC, GC, 0);
    sgemm_bias<<<dim3(BB * DD / 128, 2), 256>>>(sent, wgb_h, bgb_h, sXWg_b, BB * DD, GC, GC, 0);
    sgemm_bias<<<dim3(BB * DD / 128, 1), 256>>>(sent, wcb_h, bcb_h, sXWc_b, BB * DD, CC, GC, 0);

    // 5) sentence-level BiGRU: resident weights, 40-step loop, one launch
    gru_resident_kernel<4><<<dim3(BB / 4, 2), 256, smem_s>>>(
        sXWg_f, sXWg_b, sXWc_f, sXWc_b,
        wgf_h + (size_t)GC * GC, wgb_h + (size_t)GC * GC,
        wcf_h + (size_t)GC * CC, wcb_h + (size_t)GC * CC,
        dlen, high, DD);

    // 6) sentence attention
    sgemm_bias<<<dim3(BB * DD / 128, 1), 256>>>(high, wa_h, ba_h, proj, BB * DD, CC, GC, 1);
    attention_kernel<<<BB, 256>>>(proj, us, high, docvec, out + 66 + BD * SW, BB, DD);

    // 7) classifier / loss / reg / predict / accuracy
    final_kernel<<<1, 256>>>(docvec, wp, bp, y, wa_l, ba_l, wa_h, uw, us, out);
}